// round 7
// baseline (speedup 1.0000x reference)
#include <cuda_runtime.h>
#include <cstdint>

#define BB 128
#define TT 4096
#define KK 64
#define CHUNK 64
#define NCH   (TT / CHUNK)   /* 64 chunks */
#define GRP   8              /* chunks walked per backward group (32 KB) */

// ---- scratch (static __device__: allocation-free) ----
__device__ __align__(16) float   g_alpha[(size_t)BB * TT * KK]; // 134 MB alpha history
__device__ __align__(16) uint8_t g_bp[(size_t)BB * TT * KK];    // 32 MB backpointers
__device__ int g_lasttag[BB];

__device__ __forceinline__ void cpasync16(uint32_t saddr, const void* gptr) {
    asm volatile("cp.async.ca.shared.global [%0], [%1], 16;" :: "r"(saddr), "l"(gptr));
}
__device__ __forceinline__ void cpasync_commit() {
    asm volatile("cp.async.commit_group;");
}
__device__ __forceinline__ void cpasync_wait1() {
    asm volatile("cp.async.wait_group 1;");
}

// =====================================================================
// Kernel 1: forward Viterbi, MAX ONLY (no argmax in the serial loop).
// Alpha rows overwrite the emission buffer in place and are flushed to
// g_alpha per 64-step chunk. 128 threads = 64 k x 2 pred-halves.
// =====================================================================
__global__ __launch_bounds__(128) void fwd_kernel(const float* __restrict__ pot,
                                                  const float* __restrict__ trans) {
    const int b   = blockIdx.x;
    const int tid = threadIdx.x;
    const int k   = tid >> 1;
    const int jh  = tid & 1;

    __shared__ __align__(16) float st_s[2][KK];
    __shared__ __align__(16) float ebuf[2][CHUNK * KK];   // 32 KB emission/alpha dbuf

    float tr[32];
#pragma unroll
    for (int i = 0; i < 32; ++i) tr[i] = trans[(jh * 32 + i) * KK + k];

    const float* pb = pot + (size_t)b * TT * KK;
    float*       ab = g_alpha + (size_t)b * TT * KK;

    // prologue: prefetch emission chunks 0, 1
    {
        uint32_t s0 = (uint32_t)__cvta_generic_to_shared(ebuf[0]);
        uint32_t s1 = (uint32_t)__cvta_generic_to_shared(ebuf[1]);
#pragma unroll
        for (int i = 0; i < 8; ++i)
            cpasync16(s0 + (i * 128 + tid) * 16, pb + (i * 128 + tid) * 4);
        cpasync_commit();
#pragma unroll
        for (int i = 0; i < 8; ++i)
            cpasync16(s1 + (i * 128 + tid) * 16, pb + CHUNK * KK + (i * 128 + tid) * 4);
        cpasync_commit();
        cpasync_wait1();
    }
    __syncthreads();

    if (jh == 0) st_s[0][k] = ebuf[0][k];   // alpha_0 = emission row 0 (in place already)
    __syncthreads();

    for (int c = 0; c < NCH; ++c) {
        float* eb = ebuf[c & 1];
        const int r0 = (c == 0) ? 1 : 0;

        for (int r = r0; r < CHUNK; ++r) {
            const int t = c * CHUNK + r;
            const float* s = st_s[(t - 1) & 1] + jh * 32;

            float v[32];
#pragma unroll
            for (int i = 0; i < 8; ++i) {
                float4 s4 = ((const float4*)s)[i];
                v[4 * i + 0] = s4.x + tr[4 * i + 0];
                v[4 * i + 1] = s4.y + tr[4 * i + 1];
                v[4 * i + 2] = s4.z + tr[4 * i + 2];
                v[4 * i + 3] = s4.w + tr[4 * i + 3];
            }
            // FMNMX tree (contiguous pairs) -> exact max
            float m[16];
#pragma unroll
            for (int i = 0; i < 16; ++i) m[i] = fmaxf(v[2 * i], v[2 * i + 1]);
#pragma unroll
            for (int i = 0; i < 8; ++i)  m[i] = fmaxf(m[2 * i], m[2 * i + 1]);
#pragma unroll
            for (int i = 0; i < 4; ++i)  m[i] = fmaxf(m[2 * i], m[2 * i + 1]);
            float vmax = fmaxf(fmaxf(m[0], m[1]), fmaxf(m[2], m[3]));

            float best = fmaxf(vmax, __shfl_xor_sync(0xffffffffu, vmax, 1));

            if (jh == 0) {
                float a = best + eb[r * KK + k];
                st_s[t & 1][k] = a;
                eb[r * KK + k] = a;           // in-place alpha (cell consumed above)
            }
            __syncthreads();
        }

        // flush alpha chunk (rows 64c..64c+63; row 0 of chunk 0 already = alpha_0)
        {
            const uint4* src = (const uint4*)eb;
            uint4* dst = (uint4*)(ab + (size_t)c * CHUNK * KK);
#pragma unroll
            for (int i = 0; i < 8; ++i) dst[tid + 128 * i] = src[tid + 128 * i];
        }
        __syncthreads();   // all reads of eb complete before cp.async overwrites it
        if (c + 1 < NCH) {
            if (c + 2 < NCH) {
                uint32_t sn = (uint32_t)__cvta_generic_to_shared(eb);
                const float* gsrc = pb + (size_t)(c + 2) * CHUNK * KK;
#pragma unroll
                for (int i = 0; i < 8; ++i)
                    cpasync16(sn + (i * 128 + tid) * 16, gsrc + (i * 128 + tid) * 4);
            }
            cpasync_commit();
            cpasync_wait1();   // chunk c+1 resident
        }
        __syncthreads();
    }

    if (tid == 0) {
        const float* fin = st_s[(TT - 1) & 1];
        float bv = fin[0]; int bk = 0;
#pragma unroll
        for (int kk = 1; kk < KK; ++kk) {
            float vv = fin[kk];
            if (vv > bv) { bv = vv; bk = kk; }
        }
        g_lasttag[b] = bk;
    }
}

// =====================================================================
// Kernel 2: backpointer recompute — fully parallel over (b, chunk).
// bp[t][k] = first-index argmax_j (alpha[t-1][j] + T[j][k]).
// Bitwise-identical FADD to kernel 1 => identical values => exact argmax.
// =====================================================================
__global__ __launch_bounds__(128) void bp_kernel(const float* __restrict__ trans) {
    const int c   = blockIdx.x;
    const int b   = blockIdx.y;
    const int tid = threadIdx.x;
    const int k   = tid >> 1;
    const int jh  = tid & 1;

    __shared__ __align__(16) float   aslab[CHUNK * KK];   // 16 KB: alpha rows 64c-1..64c+62
    __shared__ __align__(16) uint8_t bps[CHUNK * KK];     // 4 KB

    float tr[32];
#pragma unroll
    for (int i = 0; i < 32; ++i) tr[i] = trans[(jh * 32 + i) * KK + k];

    const float* abase = g_alpha + (size_t)b * TT * KK;
    if (c == 0) {
        // slab rows 1..63 = alpha rows 0..62 (row 0 unused)
        float4* d = (float4*)(aslab + KK);
        const float4* s = (const float4*)abase;
        for (int i = tid; i < 63 * KK / 4; i += 128) d[i] = s[i];
        if (jh == 0) bps[k] = (uint8_t)k;   // bp row 0: placeholder (never applied)
    } else {
        const float4* s = (const float4*)(abase + ((size_t)c * CHUNK - 1) * KK);
        float4* d = (float4*)aslab;
#pragma unroll
        for (int i = 0; i < 8; ++i) d[tid + 128 * i] = s[tid + 128 * i];
    }
    __syncthreads();

    const int r0 = (c == 0) ? 1 : 0;
    for (int r = r0; r < CHUNK; ++r) {
        const float* s = aslab + r * KK + jh * 32;

        float v[32];
#pragma unroll
        for (int i = 0; i < 8; ++i) {
            float4 s4 = ((const float4*)s)[i];
            v[4 * i + 0] = s4.x + tr[4 * i + 0];
            v[4 * i + 1] = s4.y + tr[4 * i + 1];
            v[4 * i + 2] = s4.z + tr[4 * i + 2];
            v[4 * i + 3] = s4.w + tr[4 * i + 3];
        }
        float m[16];
#pragma unroll
        for (int i = 0; i < 16; ++i) m[i] = fmaxf(v[2 * i], v[2 * i + 1]);
#pragma unroll
        for (int i = 0; i < 8; ++i)  m[i] = fmaxf(m[2 * i], m[2 * i + 1]);
#pragma unroll
        for (int i = 0; i < 4; ++i)  m[i] = fmaxf(m[2 * i], m[2 * i + 1]);
        const float vmax = fmaxf(fmaxf(m[0], m[1]), fmaxf(m[2], m[3]));

        unsigned msk = 0u;
#pragma unroll
        for (int i = 0; i < 32; ++i)
            msk |= (v[i] == vmax) ? (1u << i) : 0u;
        int gj_loc = jh * 32 + (__ffs(msk) - 1);

        // merge halves (adjacent lanes); jh0 holds smaller indices -> wins ties
        float po = __shfl_xor_sync(0xffffffffu, vmax,   1);
        int   jo = __shfl_xor_sync(0xffffffffu, gj_loc, 1);
        bool take = jh ? (po >= vmax) : (po > vmax);
        int gj = take ? jo : gj_loc;

        if (jh == 0) bps[r * KK + k] = (uint8_t)gj;
    }
    __syncthreads();

    uint4* dst = (uint4*)(g_bp + (size_t)b * TT * KK + (size_t)c * CHUNK * KK);
    const uint4* src = (const uint4*)bps;
    dst[tid]       = src[tid];
    dst[tid + 128] = src[tid + 128];
}

// =====================================================================
// Kernel 3: serial backward walk per batch + sequence length.
// =====================================================================
__global__ __launch_bounds__(128) void bwd_kernel(const int* __restrict__ mask,
                                                  float* __restrict__ out) {
    const int b   = blockIdx.x;
    const int tid = threadIdx.x;

    __shared__ __align__(16) uint8_t wb[GRP][CHUNK][KK];   // 32 KB
    __shared__ __align__(16) float   tagseg[GRP * CHUNK];
    __shared__ int scur;

    if (tid == 0) scur = g_lasttag[b];

    const uint8_t* bpb = g_bp + (size_t)b * TT * KK;
    for (int base = NCH - GRP; base >= 0; base -= GRP) {
        const uint4* src = (const uint4*)(bpb + (size_t)base * CHUNK * KK);
        uint4* dst = (uint4*)wb;
#pragma unroll
        for (int i = 0; i < (GRP * CHUNK * KK / 16) / 128; ++i)
            dst[tid + 128 * i] = src[tid + 128 * i];
        __syncthreads();

        if (tid == 0) {
            int cur = scur;                 // tag at t = 64*(base+GRP) - 1
            for (int g = GRP - 1; g >= 0; --g) {
                tagseg[g * CHUNK + CHUNK - 1] = (float)cur;
                for (int r = CHUNK - 1; r >= 1; --r) {
                    cur = wb[g][r][cur];
                    tagseg[g * CHUNK + r - 1] = (float)cur;
                }
                cur = wb[g][0][cur];        // cross chunk boundary
            }
            scur = cur;
        }
        __syncthreads();

        float* ob = out + (size_t)b * TT + base * CHUNK;
#pragma unroll
        for (int i = 0; i < (GRP * CHUNK) / 128; ++i)
            ob[tid + 128 * i] = tagseg[tid + 128 * i];
        __syncthreads();
    }

    // sequence length
    {
        int s = 0;
        const int4* m = (const int4*)(mask + (size_t)b * TT);
        for (int i = tid; i < TT / 4; i += 128) {
            int4 v = m[i];
            s += v.x + v.y + v.z + v.w;
        }
#pragma unroll
        for (int off = 16; off; off >>= 1) s += __shfl_xor_sync(0xffffffffu, s, off);
        __shared__ int red[4];
        if ((tid & 31) == 0) red[tid >> 5] = s;
        __syncthreads();
        if (tid == 0)
            out[(size_t)BB * TT + b] = (float)(red[0] + red[1] + red[2] + red[3]);
    }
}

// =====================================================================
extern "C" void kernel_launch(void* const* d_in, const int* in_sizes, int n_in,
                              void* d_out, int out_size) {
    const float* pot   = nullptr;
    const float* trans = nullptr;
    const int*   mask  = nullptr;
    for (int i = 0; i < n_in; ++i) {
        if      (in_sizes[i] == BB * TT * KK) pot   = (const float*)d_in[i];
        else if (in_sizes[i] == KK * KK)      trans = (const float*)d_in[i];
        else if (in_sizes[i] == BB * TT)      mask  = (const int*)  d_in[i];
    }
    float* out = (float*)d_out;   // [tags (128*4096) | lengths (128)] as f32

    fwd_kernel<<<BB, 128>>>(pot, trans);
    bp_kernel<<<dim3(NCH, BB), 128>>>(trans);
    bwd_kernel<<<BB, 128>>>(mask, out);
}

// round 8
// speedup vs baseline: 1.1870x; 1.1870x over previous
#include <cuda_runtime.h>
#include <cstdint>

#define BB 128
#define TT 4096
#define KK 64
#define CHUNK 64
#define NCH   (TT / CHUNK)   /* 64 chunks */
#define GRP   8              /* chunks walked per backward group (32 KB) */

// scratch (static __device__: allocation-free)
__device__ __align__(16) uint8_t g_bp[(size_t)BB * TT * KK];   // 32 MB backpointers
__device__ int g_lasttag[BB];

__device__ __forceinline__ void cpasync16(uint32_t saddr, const void* gptr) {
    asm volatile("cp.async.ca.shared.global [%0], [%1], 16;" :: "r"(saddr), "l"(gptr));
}
__device__ __forceinline__ void cpasync_commit() {
    asm volatile("cp.async.commit_group;");
}
__device__ __forceinline__ void cpasync_wait1() {
    asm volatile("cp.async.wait_group 1;");
}

// packed f32x2 helpers (Blackwell)
__device__ __forceinline__ unsigned long long addx2(unsigned long long a, unsigned long long b) {
    unsigned long long d;
    asm("add.rn.f32x2 %0, %1, %2;" : "=l"(d) : "l"(a), "l"(b));
    return d;
}
__device__ __forceinline__ unsigned long long fmax2_fma(unsigned long long a, unsigned long long b,
                                                        unsigned long long c) {
    unsigned long long d;
    asm("fma.rn.f32x2 %0, %1, %2, %3;" : "=l"(d) : "l"(a), "l"(b), "l"(c));
    return d;
}
__device__ __forceinline__ float lo32(unsigned long long x) { return __uint_as_float((unsigned)x); }
__device__ __forceinline__ float hi32(unsigned long long x) { return __uint_as_float((unsigned)(x >> 32)); }
__device__ __forceinline__ unsigned ulo(unsigned long long x) { return (unsigned)x; }
__device__ __forceinline__ unsigned uhi(unsigned long long x) { return (unsigned)(x >> 32); }

#define NEG1X2 0xBF800000BF800000ULL   /* (-1.0f, -1.0f) */

// =====================================================================
// Fused forward Viterbi with integer-key argmax.
// 1 CTA per batch, 128 threads = 64 k-columns x 2 predecessor halves.
// bp[t][k] = first-index argmax_j (alpha[t-1][j] + T[j][k])   (exact)
// Key trick: d_i = vmax - v_i (packed fma, fma pipe), key_i = bits(d)*2+i;
// min key == first index of maximum (d==+0 iff v_i==vmax; *2 clears -0).
// =====================================================================
__global__ __launch_bounds__(128) void fwd_kernel(const float* __restrict__ pot,
                                                  const float* __restrict__ trans) {
    const int b   = blockIdx.x;
    const int tid = threadIdx.x;
    const int k   = tid >> 1;   // 0..63
    const int jh  = tid & 1;    // 0..1

    __shared__ __align__(16) float   st_s[2][KK];
    __shared__ __align__(16) float   ebuf[2][CHUNK * KK];   // 32 KB emission dbuf
    __shared__ __align__(16) uint8_t bps[CHUNK][KK];        // 4 KB bp staging

    // packed transition pairs: trp[i] = (T[jh*32+2i][k], T[jh*32+2i+1][k])
    unsigned long long trp[16];
#pragma unroll
    for (int i = 0; i < 16; ++i) {
        unsigned a = __float_as_uint(trans[(jh * 32 + 2 * i) * KK + k]);
        unsigned c = __float_as_uint(trans[(jh * 32 + 2 * i + 1) * KK + k]);
        trp[i] = (unsigned long long)a | ((unsigned long long)c << 32);
    }

    const float* pb  = pot + (size_t)b * TT * KK;
    uint8_t*     bpb = g_bp + (size_t)b * TT * KK;

    // prologue: prefetch emission chunks 0, 1
    {
        uint32_t s0 = (uint32_t)__cvta_generic_to_shared(ebuf[0]);
        uint32_t s1 = (uint32_t)__cvta_generic_to_shared(ebuf[1]);
#pragma unroll
        for (int i = 0; i < 8; ++i)
            cpasync16(s0 + (i * 128 + tid) * 16, pb + (i * 128 + tid) * 4);
        cpasync_commit();
#pragma unroll
        for (int i = 0; i < 8; ++i)
            cpasync16(s1 + (i * 128 + tid) * 16, pb + CHUNK * KK + (i * 128 + tid) * 4);
        cpasync_commit();
        cpasync_wait1();
    }
    __syncthreads();

    if (jh == 0) {
        st_s[0][k] = ebuf[0][k];   // alpha_0
        bps[0][k]  = (uint8_t)k;   // row-0 placeholder (never applied)
    }
    __syncthreads();

    for (int c = 0; c < NCH; ++c) {
        const float* eb = ebuf[c & 1];
        const int r0 = (c == 0) ? 1 : 0;

        for (int r = r0; r < CHUNK; ++r) {
            const int t = c * CHUNK + r;
            const float* s = st_s[(t - 1) & 1] + jh * 32;

            // v = state + transitions, packed f32x2 (fma pipe)
            unsigned long long vp[16];
#pragma unroll
            for (int i = 0; i < 8; ++i) {
                ulonglong2 sv = ((const ulonglong2*)s)[i];   // LDS.128
                vp[2 * i]     = addx2(sv.x, trp[2 * i]);
                vp[2 * i + 1] = addx2(sv.y, trp[2 * i + 1]);
            }

            // vmax: FMNMX tree (alu pipe), exact max
            float mx[16];
#pragma unroll
            for (int i = 0; i < 16; ++i) mx[i] = fmaxf(lo32(vp[i]), hi32(vp[i]));
#pragma unroll
            for (int i = 0; i < 8; ++i)  mx[i] = fmaxf(mx[2 * i], mx[2 * i + 1]);
#pragma unroll
            for (int i = 0; i < 4; ++i)  mx[i] = fmaxf(mx[2 * i], mx[2 * i + 1]);
            const float vmax = fmaxf(fmaxf(mx[0], mx[1]), fmaxf(mx[2], mx[3]));

            // d = vmax - v  (packed fma: v*(-1)+vmax); key = bits(d)*2 + idx
            unsigned long long vmaxp;
            asm("mov.b64 %0, {%1, %1};" : "=l"(vmaxp) : "r"(__float_as_uint(vmax)));
            unsigned key[32];
#pragma unroll
            for (int i = 0; i < 16; ++i) {
                unsigned long long dp = fmax2_fma(vp[i], NEG1X2, vmaxp);
                key[2 * i]     = ulo(dp) * 2u + (unsigned)(2 * i);
                key[2 * i + 1] = uhi(dp) * 2u + (unsigned)(2 * i + 1);
            }
            // min-key tree (IMNMX, alu pipe) -> first index of maximum
#pragma unroll
            for (int i = 0; i < 16; ++i) key[i] = umin(key[2 * i], key[2 * i + 1]);
#pragma unroll
            for (int i = 0; i < 8; ++i)  key[i] = umin(key[2 * i], key[2 * i + 1]);
#pragma unroll
            for (int i = 0; i < 4; ++i)  key[i] = umin(key[2 * i], key[2 * i + 1]);
            const unsigned kmin = umin(umin(key[0], key[1]), umin(key[2], key[3]));

            float best = vmax;
            int   gj   = jh * 32 + (int)kmin;   // kmin <= 31 (winner has d==+0)

            // merge the two halves; jh0 holds smaller indices -> wins ties
            float po = __shfl_xor_sync(0xffffffffu, best, 1);
            int   jo = __shfl_xor_sync(0xffffffffu, gj,   1);
            bool take = jh ? (po >= best) : (po > best);
            best = fmaxf(best, po);
            gj   = take ? jo : gj;

            if (jh == 0) {
                st_s[t & 1][k] = best + eb[r * KK + k];
                bps[r][k]      = (uint8_t)gj;
            }
            __syncthreads();
        }

        // chunk boundary: flush bp chunk, prefetch chunk c+2, sync chunk c+1
        {
            uint4*       dst = (uint4*)(bpb + (size_t)c * CHUNK * KK);
            const uint4* src = (const uint4*)bps;
            dst[tid]       = src[tid];
            dst[tid + 128] = src[tid + 128];
        }
        if (c + 1 < NCH) {
            if (c + 2 < NCH) {
                // chunk c+2 shares parity with chunk c -> reuse its buffer
                float* enb = ebuf[c & 1];
                uint32_t sn = (uint32_t)__cvta_generic_to_shared(enb);
                const float* gsrc = pb + (size_t)(c + 2) * CHUNK * KK;
#pragma unroll
                for (int i = 0; i < 8; ++i)
                    cpasync16(sn + (i * 128 + tid) * 16, gsrc + (i * 128 + tid) * 4);
            }
            cpasync_commit();
            cpasync_wait1();   // chunk c+1 resident
        }
        __syncthreads();
    }

    if (tid == 0) {
        const float* fin = st_s[(TT - 1) & 1];
        float bv = fin[0]; int bk = 0;
#pragma unroll
        for (int kk = 1; kk < KK; ++kk) {
            float vv = fin[kk];
            if (vv > bv) { bv = vv; bk = kk; }
        }
        g_lasttag[b] = bk;
    }
}

// =====================================================================
// Backward: serial walk per batch through shared reloads + lengths.
// =====================================================================
__global__ __launch_bounds__(128) void bwd_kernel(const int* __restrict__ mask,
                                                  float* __restrict__ out) {
    const int b   = blockIdx.x;
    const int tid = threadIdx.x;

    __shared__ __align__(16) uint8_t wb[GRP][CHUNK][KK];   // 32 KB
    __shared__ __align__(16) float   tagseg[GRP * CHUNK];
    __shared__ int scur;

    if (tid == 0) scur = g_lasttag[b];

    const uint8_t* bpb = g_bp + (size_t)b * TT * KK;
    for (int base = NCH - GRP; base >= 0; base -= GRP) {
        const uint4* src = (const uint4*)(bpb + (size_t)base * CHUNK * KK);
        uint4* dst = (uint4*)wb;
#pragma unroll
        for (int i = 0; i < (GRP * CHUNK * KK / 16) / 128; ++i)
            dst[tid + 128 * i] = src[tid + 128 * i];
        __syncthreads();

        if (tid == 0) {
            int cur = scur;                 // tag at t = 64*(base+GRP) - 1
            for (int g = GRP - 1; g >= 0; --g) {
                tagseg[g * CHUNK + CHUNK - 1] = (float)cur;
                for (int r = CHUNK - 1; r >= 1; --r) {
                    cur = wb[g][r][cur];
                    tagseg[g * CHUNK + r - 1] = (float)cur;
                }
                cur = wb[g][0][cur];        // cross chunk boundary
            }
            scur = cur;
        }
        __syncthreads();

        float* ob = out + (size_t)b * TT + base * CHUNK;
#pragma unroll
        for (int i = 0; i < (GRP * CHUNK) / 128; ++i)
            ob[tid + 128 * i] = tagseg[tid + 128 * i];
        __syncthreads();
    }

    // sequence length
    {
        int s = 0;
        const int4* m = (const int4*)(mask + (size_t)b * TT);
        for (int i = tid; i < TT / 4; i += 128) {
            int4 v = m[i];
            s += v.x + v.y + v.z + v.w;
        }
#pragma unroll
        for (int off = 16; off; off >>= 1) s += __shfl_xor_sync(0xffffffffu, s, off);
        __shared__ int red[4];
        if ((tid & 31) == 0) red[tid >> 5] = s;
        __syncthreads();
        if (tid == 0)
            out[(size_t)BB * TT + b] = (float)(red[0] + red[1] + red[2] + red[3]);
    }
}

// =====================================================================
extern "C" void kernel_launch(void* const* d_in, const int* in_sizes, int n_in,
                              void* d_out, int out_size) {
    const float* pot   = nullptr;
    const float* trans = nullptr;
    const int*   mask  = nullptr;
    for (int i = 0; i < n_in; ++i) {
        if      (in_sizes[i] == BB * TT * KK) pot   = (const float*)d_in[i];
        else if (in_sizes[i] == KK * KK)      trans = (const float*)d_in[i];
        else if (in_sizes[i] == BB * TT)      mask  = (const int*)  d_in[i];
    }
    float* out = (float*)d_out;   // [tags (128*4096) | lengths (128)] as f32

    fwd_kernel<<<BB, 128>>>(pot, trans);
    bwd_kernel<<<BB, 128>>>(mask, out);
}